// round 1
// baseline (speedup 1.0000x reference)
#include <cuda_runtime.h>
#include <cuda_bf16.h>
#include <math.h>

// ----------------------------------------------------------------------------
// AdaptiveFeaturePropagation
//   in0: current_frame_low_features (2,128,33,33) f32
//   in1: key_frame_low_features     (2,128,33,33) f32
//   in2: key_frame_high_features    (2,256,129,129) f32
//   in3: w_reduce (256,128,3,3)  in4: b_reduce (256)
//   in5: w_conv2  (256,512,3,3)  in6: b_conv2 (256)
//   in7: w_conv3  (49,256,1,1)   in8: b_conv3 (49)
//   out: (2,256,129,129) f32
// ----------------------------------------------------------------------------

#define Hc 129
#define Wc 129
#define HWc (129*129)
#define HIN 33

// scratch (allocation-free rule: __device__ globals)
__device__ float g_cur_up[2*128*HWc];
__device__ float g_key_up[2*128*HWc];
__device__ float g_concat[2*512*HWc];
__device__ float g_x2[2*256*HWc];
__device__ float g_kern[2*49*HWc];
__device__ float g_wrT[128*9*256];
__device__ float g_w2T[512*9*256];

// ---------------------------------------------------------------- upsample --
__global__ void upsample_kernel(const float* __restrict__ in,
                                float* __restrict__ out, int total)
{
    int idx = blockIdx.x * blockDim.x + threadIdx.x;
    if (idx >= total) return;
    int pix = idx % HWc;
    int nc  = idx / HWc;
    int y = pix / Wc, x = pix % Wc;
    const float s = 33.0f / 129.0f;
    float sy = (y + 0.5f) * s - 0.5f;
    float sx = (x + 0.5f) * s - 0.5f;
    float fy = floorf(sy), fx = floorf(sx);
    int y0 = (int)fy, x0 = (int)fx;
    float wy = sy - fy, wx = sx - fx;
    int y0c = max(y0, 0), y1c = min(y0 + 1, HIN - 1);
    int x0c = max(x0, 0), x1c = min(x0 + 1, HIN - 1);
    const float* p = in + nc * (HIN * HIN);
    float v00 = p[y0c * HIN + x0c];
    float v01 = p[y0c * HIN + x1c];
    float v10 = p[y1c * HIN + x0c];
    float v11 = p[y1c * HIN + x1c];
    float v0 = v00 + (v01 - v00) * wx;
    float v1 = v10 + (v11 - v10) * wx;
    out[idx] = v0 + (v1 - v0) * wy;
}

// --------------------------------------------------- weight pre-transpose  --
// in:  OIHW  (OC, CIN, 3, 3)
// out: [(ic*9 + k)][OC]   (oc contiguous -> coalesced smem fills in conv)
__global__ void transpose_w_kernel(const float* __restrict__ in,
                                   float* __restrict__ out, int OC, int CIN)
{
    int idx = blockIdx.x * blockDim.x + threadIdx.x;
    int total = OC * CIN * 9;
    if (idx >= total) return;
    int oc = idx / (CIN * 9);
    int r  = idx % (CIN * 9);         // ic*9 + k
    out[r * OC + oc] = in[idx];
}

// ------------------------------------------------------------- 3x3 conv    --
// Block: 64 output channels x (8 rows x 16 cols) pixel tile, 256 threads.
// Thread: 4 oc x 8 px. Double-buffered smem, 4 input channels per stage.
template<int CIN>
__global__ __launch_bounds__(256)
void conv3x3_relu_kernel(const float* __restrict__ in,
                         const float* __restrict__ wT,   // [(ic*9+k)*256 + oc]
                         const float* __restrict__ bias,
                         float* __restrict__ out,
                         int in_img_stride, int out_img_stride)
{
    constexpr int ICS = 4;
    constexpr int PITCH = 19;               // 18 used, padded (conflict-free)
    __shared__ float s_in[2][ICS][10 * PITCH];
    __shared__ __align__(16) float s_w[2][ICS][9][64];

    const int tid = threadIdx.x;
    const int tx0 = blockIdx.x * 16;
    const int ty0 = blockIdx.y * 8;
    const int n   = blockIdx.z >> 2;
    const int ocb = blockIdx.z & 3;
    const float* inb = in + n * in_img_stride;
    float* outb = out + n * out_img_stride + (ocb * 64) * HWc;
    const int oc_g = ocb * 64;

    const int tid_oc = tid >> 4;            // 0..15
    const int tid_px = tid & 15;            // 0..15
    const int oc0 = tid_oc * 4;
    const int row = tid_px >> 1;            // 0..7
    const int col0 = (tid_px & 1) * 8;      // 0 or 8

    float acc[4][8];
#pragma unroll
    for (int o = 0; o < 4; o++)
#pragma unroll
        for (int p = 0; p < 8; p++) acc[o][p] = 0.f;

    float b[4];
#pragma unroll
    for (int o = 0; o < 4; o++) b[o] = bias[oc_g + oc0 + o];

    const int NSTAGE = CIN / ICS;
    for (int s = 0; s < NSTAGE; s++) {
        const int buf = s & 1;
        const int ic0 = s * ICS;
        // input patch: ICS x 10 x 18
        for (int idx = tid; idx < ICS * 10 * 18; idx += 256) {
            int icl = idx / 180;
            int r   = (idx / 18) % 10;
            int c   = idx % 18;
            int gy = ty0 - 1 + r, gx = tx0 - 1 + c;
            float v = 0.f;
            if ((unsigned)gy < Hc && (unsigned)gx < Wc)
                v = inb[(ic0 + icl) * HWc + gy * Wc + gx];
            s_in[buf][icl][r * PITCH + c] = v;
        }
        // weights: ICS x 9 x 64 (coalesced from transposed layout)
        for (int idx = tid; idx < ICS * 9 * 64; idx += 256) {
            int icl = idx / (9 * 64);
            int k   = (idx / 64) % 9;
            int ocl = idx % 64;
            s_w[buf][icl][k][ocl] = wT[((ic0 + icl) * 9 + k) * 256 + oc_g + ocl];
        }
        __syncthreads();
#pragma unroll
        for (int icl = 0; icl < ICS; icl++) {
#pragma unroll
            for (int kh = 0; kh < 3; kh++) {
                float ir[10];
#pragma unroll
                for (int i = 0; i < 10; i++)
                    ir[i] = s_in[buf][icl][(row + kh) * PITCH + col0 + i];
#pragma unroll
                for (int kw = 0; kw < 3; kw++) {
                    float4 w4 = *(const float4*)&s_w[buf][icl][kh * 3 + kw][oc0];
                    float wv0 = w4.x, wv1 = w4.y, wv2 = w4.z, wv3 = w4.w;
#pragma unroll
                    for (int p = 0; p < 8; p++) {
                        float iv = ir[p + kw];
                        acc[0][p] += wv0 * iv;
                        acc[1][p] += wv1 * iv;
                        acc[2][p] += wv2 * iv;
                        acc[3][p] += wv3 * iv;
                    }
                }
            }
        }
    }
    const int y = ty0 + row;
#pragma unroll
    for (int o = 0; o < 4; o++) {
#pragma unroll
        for (int p = 0; p < 8; p++) {
            int x = tx0 + col0 + p;
            if (y < Hc && x < Wc)
                outb[(oc0 + o) * HWc + y * Wc + x] = fmaxf(acc[o][p] + b[o], 0.f);
        }
    }
}

// --------------------------------------------- 1x1 conv + relu + softmax   --
// one thread per pixel; 49 accumulators; weights staged in dynamic smem
__global__ __launch_bounds__(256)
void conv3_softmax_kernel(const float* __restrict__ x,
                          const float* __restrict__ w3,   // (49,256)
                          const float* __restrict__ b3,
                          float* __restrict__ kout)
{
    extern __shared__ float ws[];           // [c*49 + oc], 12544 floats
    for (int idx = threadIdx.x; idx < 256 * 49; idx += 256) {
        int c = idx / 49, oc = idx % 49;
        ws[idx] = w3[oc * 256 + c];
    }
    __syncthreads();

    int p = blockIdx.x * 256 + threadIdx.x;
    if (p >= 2 * HWc) return;
    int n = p / HWc, pix = p % HWc;
    const float* xb = x + n * 256 * HWc + pix;

    float acc[49];
#pragma unroll
    for (int oc = 0; oc < 49; oc++) acc[oc] = 0.f;

    for (int c = 0; c < 256; c++) {
        float xv = xb[c * HWc];
        const float* wr = &ws[c * 49];
#pragma unroll
        for (int oc = 0; oc < 49; oc++) acc[oc] += xv * wr[oc];
    }
    float m = -1e30f;
#pragma unroll
    for (int oc = 0; oc < 49; oc++) {
        acc[oc] = fmaxf(acc[oc] + b3[oc], 0.f);
        m = fmaxf(m, acc[oc]);
    }
    float ssum = 0.f;
#pragma unroll
    for (int oc = 0; oc < 49; oc++) {
        acc[oc] = __expf(acc[oc] - m);
        ssum += acc[oc];
    }
    float inv = 1.f / ssum;
    float* kb = kout + n * 49 * HWc + pix;
#pragma unroll
    for (int oc = 0; oc < 49; oc++) kb[oc * HWc] = acc[oc] * inv;
}

// --------------------------------------------- spatially-variant 7x7 conv  --
// Block: 16x16 pixel tile x 64-channel chunk. kernel weights (49) in regs.
__global__ __launch_bounds__(256)
void svconv_kernel(const float* __restrict__ feat,
                   const float* __restrict__ kern,
                   float* __restrict__ out)
{
    constexpr int TS = 16, PAD = 3, FT = TS + 2 * PAD;   // 22
    __shared__ float sf[2][FT * FT];

    const int tid = threadIdx.x;
    const int txi = tid & 15, tyi = tid >> 4;
    const int bx = blockIdx.x * TS, by = blockIdx.y * TS;
    const int n = blockIdx.z >> 2;
    const int c0 = (blockIdx.z & 3) * 64;
    const int x = bx + txi, y = by + tyi;
    const bool valid = (x < Wc) && (y < Hc);

    float kv[49];
    if (valid) {
        const float* kb = kern + n * 49 * HWc + y * Wc + x;
#pragma unroll
        for (int t = 0; t < 49; t++) kv[t] = kb[t * HWc];
    } else {
#pragma unroll
        for (int t = 0; t < 49; t++) kv[t] = 0.f;
    }

    const float* fb = feat + (n * 256 + c0) * HWc;
    float* ob = out + (n * 256 + c0) * HWc;

    for (int cl = 0; cl < 64; cl++) {
        const int buf = cl & 1;
        const float* fc = fb + cl * HWc;
        for (int idx = tid; idx < FT * FT; idx += 256) {
            int r = idx / FT, cc = idx % FT;
            int gy = by - PAD + r, gx = bx - PAD + cc;
            float v = 0.f;
            if ((unsigned)gy < Hc && (unsigned)gx < Wc) v = fc[gy * Wc + gx];
            sf[buf][idx] = v;
        }
        __syncthreads();
        if (valid) {
            float a = 0.f;
#pragma unroll
            for (int i = 0; i < 7; i++)
#pragma unroll
                for (int j = 0; j < 7; j++)
                    a += kv[i * 7 + j] * sf[buf][(tyi + i) * FT + txi + j];
            ob[cl * HWc + y * Wc + x] = a;
        }
    }
}

// ---------------------------------------------------------------------------
extern "C" void kernel_launch(void* const* d_in, const int* in_sizes, int n_in,
                              void* d_out, int out_size)
{
    const float* cur_low  = (const float*)d_in[0];
    const float* key_low  = (const float*)d_in[1];
    const float* key_high = (const float*)d_in[2];
    const float* w_reduce = (const float*)d_in[3];
    const float* b_reduce = (const float*)d_in[4];
    const float* w_conv2  = (const float*)d_in[5];
    const float* b_conv2  = (const float*)d_in[6];
    const float* w_conv3  = (const float*)d_in[7];
    const float* b_conv3  = (const float*)d_in[8];
    float* out = (float*)d_out;

    float *cur_up, *key_up, *concat, *x2, *kern, *wrT, *w2T;
    cudaGetSymbolAddress((void**)&cur_up, g_cur_up);
    cudaGetSymbolAddress((void**)&key_up, g_key_up);
    cudaGetSymbolAddress((void**)&concat, g_concat);
    cudaGetSymbolAddress((void**)&x2, g_x2);
    cudaGetSymbolAddress((void**)&kern, g_kern);
    cudaGetSymbolAddress((void**)&wrT, g_wrT);
    cudaGetSymbolAddress((void**)&w2T, g_w2T);

    // weight pre-transpose
    {
        int t1 = 256 * 128 * 9;
        transpose_w_kernel<<<(t1 + 255) / 256, 256>>>(w_reduce, wrT, 256, 128);
        int t2 = 256 * 512 * 9;
        transpose_w_kernel<<<(t2 + 255) / 256, 256>>>(w_conv2, w2T, 256, 512);
    }
    // upsample both low-feature tensors
    {
        int total = 2 * 128 * HWc;
        upsample_kernel<<<(total + 255) / 256, 256>>>(cur_low, cur_up, total);
        upsample_kernel<<<(total + 255) / 256, 256>>>(key_low, key_up, total);
    }
    // conv_reduce (shared weights), writing directly into concat layout
    {
        dim3 grid(9, 17, 8);   // 16-wide x 8-tall tiles, z = n(2) * ocb(4)
        conv3x3_relu_kernel<128><<<grid, 256>>>(
            cur_up, wrT, b_reduce, concat, 128 * HWc, 512 * HWc);
        conv3x3_relu_kernel<128><<<grid, 256>>>(
            key_up, wrT, b_reduce, concat + 256 * HWc, 128 * HWc, 512 * HWc);
    }
    // conv2: 512 -> 256
    {
        dim3 grid(9, 17, 8);
        conv3x3_relu_kernel<512><<<grid, 256>>>(
            concat, w2T, b_conv2, x2, 512 * HWc, 256 * HWc);
    }
    // conv3 (1x1, 256->49) + relu + softmax
    {
        int smem = 256 * 49 * sizeof(float);
        cudaFuncSetAttribute(conv3_softmax_kernel,
                             cudaFuncAttributeMaxDynamicSharedMemorySize, smem);
        int total = 2 * HWc;
        conv3_softmax_kernel<<<(total + 255) / 256, 256, smem>>>(
            x2, w_conv3, b_conv3, kern);
    }
    // spatially-variant 7x7 conv
    {
        dim3 grid(9, 9, 8);    // 16x16 tiles, z = n(2) * cchunk(4)
        svconv_kernel<<<grid, 256>>>(key_high, kern, out);
    }
}

// round 3
// speedup vs baseline: 1.1715x; 1.1715x over previous
#include <cuda_runtime.h>
#include <cuda_bf16.h>
#include <math.h>

// ----------------------------------------------------------------------------
// AdaptiveFeaturePropagation  (f32x2 packed-FMA version)
// ----------------------------------------------------------------------------

#define Hc 129
#define Wc 129
#define HWc (129*129)
#define HIN 33

typedef unsigned long long u64;

__device__ __forceinline__ u64 fma2(u64 a, u64 b, u64 c) {
    u64 d;
    asm("fma.rn.f32x2 %0, %1, %2, %3;" : "=l"(d) : "l"(a), "l"(b), "l"(c));
    return d;
}
__device__ __forceinline__ u64 pack2(float lo, float hi) {
    u64 d;
    asm("mov.b64 %0, {%1, %2};" : "=l"(d) : "f"(lo), "f"(hi));
    return d;
}
__device__ __forceinline__ float2 unpack2(u64 v) {
    float2 r;
    asm("mov.b64 {%0, %1}, %2;" : "=f"(r.x), "=f"(r.y) : "l"(v));
    return r;
}

// scratch (allocation-free rule: __device__ globals)
__device__ float g_cur_up[2*128*HWc];
__device__ float g_key_up[2*128*HWc];
__device__ float g_concat[2*512*HWc];
__device__ float g_x2[2*256*HWc];
__device__ float g_kern[2*49*HWc];
__device__ float g_wrT[128*9*256];
__device__ float g_w2T[512*9*256];

// ---------------------------------------------------------------- upsample --
__global__ void upsample_kernel(const float* __restrict__ in,
                                float* __restrict__ out, int total)
{
    int idx = blockIdx.x * blockDim.x + threadIdx.x;
    if (idx >= total) return;
    int pix = idx % HWc;
    int nc  = idx / HWc;
    int y = pix / Wc, x = pix % Wc;
    const float s = 33.0f / 129.0f;
    float sy = (y + 0.5f) * s - 0.5f;
    float sx = (x + 0.5f) * s - 0.5f;
    float fy = floorf(sy), fx = floorf(sx);
    int y0 = (int)fy, x0 = (int)fx;
    float wy = sy - fy, wx = sx - fx;
    int y0c = max(y0, 0), y1c = min(y0 + 1, HIN - 1);
    int x0c = max(x0, 0), x1c = min(x0 + 1, HIN - 1);
    const float* p = in + nc * (HIN * HIN);
    float v00 = p[y0c * HIN + x0c];
    float v01 = p[y0c * HIN + x1c];
    float v10 = p[y1c * HIN + x0c];
    float v11 = p[y1c * HIN + x1c];
    float v0 = v00 + (v01 - v00) * wx;
    float v1 = v10 + (v11 - v10) * wx;
    out[idx] = v0 + (v1 - v0) * wy;
}

// --------------------------------------------------- weight pre-transpose  --
// in:  [OC][R]  (R = CIN*9) -> out: [R][OC]   (tiled smem transpose)
__global__ void transpose_w_kernel(const float* __restrict__ in,
                                   float* __restrict__ out, int OC, int R)
{
    __shared__ float tile[32][33];
    int xc = blockIdx.x * 32 + threadIdx.x;   // column index into in (r)
    int yr = blockIdx.y * 32 + threadIdx.y;   // row index into in (oc)
#pragma unroll
    for (int j = 0; j < 32; j += 8) {
        int oc = yr + j;
        if (oc < OC && xc < R)
            tile[threadIdx.y + j][threadIdx.x] = in[oc * R + xc];
    }
    __syncthreads();
    int oc = blockIdx.y * 32 + threadIdx.x;
    int r0 = blockIdx.x * 32 + threadIdx.y;
#pragma unroll
    for (int j = 0; j < 32; j += 8) {
        int r = r0 + j;
        if (r < R && oc < OC)
            out[r * OC + oc] = tile[threadIdx.x][threadIdx.y + j];
    }
}

// ------------------------------------------------------------- 3x3 conv    --
// Block: 64 oc x (8 rows x 16 cols), 256 threads. Thread: 4 oc x 8 px.
// Packed f32x2: pair = two adjacent output channels (weights load as LDS.64,
// no packing); input value dup-packed once per tap row.
template<int CIN>
__global__ __launch_bounds__(256)
void conv3x3_relu_kernel(const float* __restrict__ in,
                         const float* __restrict__ wT,   // [(ic*9+k)*256 + oc]
                         const float* __restrict__ bias,
                         float* __restrict__ out,
                         int in_img_stride, int out_img_stride)
{
    constexpr int ICS = 4;
    constexpr int PITCH = 19;
    __shared__ float s_in[2][ICS][10 * PITCH];
    __shared__ __align__(16) float s_w[2][ICS][9][64];

    const int tid = threadIdx.x;
    const int tx0 = blockIdx.x * 16;
    const int ty0 = blockIdx.y * 8;
    const int n   = blockIdx.z >> 2;
    const int ocb = blockIdx.z & 3;
    const float* inb = in + n * in_img_stride;
    float* outb = out + n * out_img_stride + (ocb * 64) * HWc;
    const int oc_g = ocb * 64;

    const int tid_oc = tid >> 4;            // 0..15
    const int tid_px = tid & 15;            // 0..15
    const int oc0 = tid_oc * 4;
    const int row = tid_px >> 1;            // 0..7
    const int col0 = (tid_px & 1) * 8;      // 0 or 8

    u64 acc2[2][8];                          // [oc-pair][pixel]
#pragma unroll
    for (int o = 0; o < 2; o++)
#pragma unroll
        for (int p = 0; p < 8; p++) acc2[o][p] = 0ull;

    const int NSTAGE = CIN / ICS;
    for (int s = 0; s < NSTAGE; s++) {
        const int buf = s & 1;
        const int ic0 = s * ICS;
        for (int idx = tid; idx < ICS * 10 * 18; idx += 256) {
            int icl = idx / 180;
            int r   = (idx / 18) % 10;
            int c   = idx % 18;
            int gy = ty0 - 1 + r, gx = tx0 - 1 + c;
            float v = 0.f;
            if ((unsigned)gy < Hc && (unsigned)gx < Wc)
                v = inb[(ic0 + icl) * HWc + gy * Wc + gx];
            s_in[buf][icl][r * PITCH + c] = v;
        }
        for (int idx = tid; idx < ICS * 9 * 64; idx += 256) {
            int icl = idx / (9 * 64);
            int k   = (idx / 64) % 9;
            int ocl = idx % 64;
            s_w[buf][icl][k][ocl] = wT[((ic0 + icl) * 9 + k) * 256 + oc_g + ocl];
        }
        __syncthreads();
#pragma unroll
        for (int icl = 0; icl < ICS; icl++) {
#pragma unroll
            for (int kh = 0; kh < 3; kh++) {
                float ir[10];
#pragma unroll
                for (int i = 0; i < 10; i++)
                    ir[i] = s_in[buf][icl][(row + kh) * PITCH + col0 + i];
                u64 dup[10];
#pragma unroll
                for (int i = 0; i < 10; i++) dup[i] = pack2(ir[i], ir[i]);
#pragma unroll
                for (int kw = 0; kw < 3; kw++) {
                    const u64* wp = (const u64*)&s_w[buf][icl][kh * 3 + kw][oc0];
                    u64 w01 = wp[0];
                    u64 w23 = wp[1];
#pragma unroll
                    for (int p = 0; p < 8; p++) {
                        acc2[0][p] = fma2(w01, dup[p + kw], acc2[0][p]);
                        acc2[1][p] = fma2(w23, dup[p + kw], acc2[1][p]);
                    }
                }
            }
        }
    }
    float b[4];
#pragma unroll
    for (int o = 0; o < 4; o++) b[o] = bias[oc_g + oc0 + o];

    const int y = ty0 + row;
#pragma unroll
    for (int o = 0; o < 2; o++) {
#pragma unroll
        for (int p = 0; p < 8; p++) {
            int x = tx0 + col0 + p;
            if (y < Hc && x < Wc) {
                float2 v = unpack2(acc2[o][p]);
                outb[(oc0 + 2 * o)     * HWc + y * Wc + x] = fmaxf(v.x + b[2 * o],     0.f);
                outb[(oc0 + 2 * o + 1) * HWc + y * Wc + x] = fmaxf(v.y + b[2 * o + 1], 0.f);
            }
        }
    }
}

// --------------------------------------------- 1x1 conv + relu + softmax   --
// one thread per pixel; packed f32x2 over oc pairs (rows padded to 50 floats)
__global__ __launch_bounds__(256)
void conv3_softmax_kernel(const float* __restrict__ x,
                          const float* __restrict__ w3,   // (49,256)
                          const float* __restrict__ b3,
                          float* __restrict__ kout)
{
    extern __shared__ float ws[];           // [c*50 + oc], 12800 floats
    for (int idx = threadIdx.x; idx < 256 * 50; idx += 256) {
        int c = idx / 50, oc = idx % 50;
        ws[idx] = (oc < 49) ? w3[oc * 256 + c] : 0.f;
    }
    __syncthreads();

    int p = blockIdx.x * 256 + threadIdx.x;
    if (p >= 2 * HWc) return;
    int n = p / HWc, pix = p % HWc;
    const float* xb = x + n * 256 * HWc + pix;

    u64 acc2[24];
#pragma unroll
    for (int q = 0; q < 24; q++) acc2[q] = 0ull;
    float acc48 = 0.f;

#pragma unroll 4
    for (int c = 0; c < 256; c++) {
        float xv = xb[c * HWc];
        u64 xd = pack2(xv, xv);
        const u64* wr = (const u64*)&ws[c * 50];
#pragma unroll
        for (int q = 0; q < 24; q++) acc2[q] = fma2(wr[q], xd, acc2[q]);
        acc48 += xv * ws[c * 50 + 48];
    }

    float a[49];
#pragma unroll
    for (int q = 0; q < 24; q++) {
        float2 v = unpack2(acc2[q]);
        a[2 * q] = v.x; a[2 * q + 1] = v.y;
    }
    a[48] = acc48;

    float m = -1e30f;
#pragma unroll
    for (int oc = 0; oc < 49; oc++) {
        a[oc] = fmaxf(a[oc] + b3[oc], 0.f);
        m = fmaxf(m, a[oc]);
    }
    float ssum = 0.f;
#pragma unroll
    for (int oc = 0; oc < 49; oc++) {
        a[oc] = __expf(a[oc] - m);
        ssum += a[oc];
    }
    float inv = 1.f / ssum;
    float* kb = kout + n * 49 * HWc + pix;
#pragma unroll
    for (int oc = 0; oc < 49; oc++) kb[oc * HWc] = a[oc] * inv;
}

// --------------------------------------------- spatially-variant 7x7 conv  --
__global__ __launch_bounds__(256)
void svconv_kernel(const float* __restrict__ feat,
                   const float* __restrict__ kern,
                   float* __restrict__ out)
{
    constexpr int TS = 16, PAD = 3, FT = TS + 2 * PAD;   // 22
    __shared__ float sf[2][FT * FT];

    const int tid = threadIdx.x;
    const int txi = tid & 15, tyi = tid >> 4;
    const int bx = blockIdx.x * TS, by = blockIdx.y * TS;
    const int n = blockIdx.z >> 2;
    const int c0 = (blockIdx.z & 3) * 64;
    const int x = bx + txi, y = by + tyi;
    const bool valid = (x < Wc) && (y < Hc);

    float kv[49];
    if (valid) {
        const float* kb = kern + n * 49 * HWc + y * Wc + x;
#pragma unroll
        for (int t = 0; t < 49; t++) kv[t] = kb[t * HWc];
    } else {
#pragma unroll
        for (int t = 0; t < 49; t++) kv[t] = 0.f;
    }

    const float* fb = feat + (n * 256 + c0) * HWc;
    float* ob = out + (n * 256 + c0) * HWc;

    for (int cl = 0; cl < 64; cl++) {
        const int buf = cl & 1;
        const float* fc = fb + cl * HWc;
        for (int idx = tid; idx < FT * FT; idx += 256) {
            int r = idx / FT, cc = idx % FT;
            int gy = by - PAD + r, gx = bx - PAD + cc;
            float v = 0.f;
            if ((unsigned)gy < Hc && (unsigned)gx < Wc) v = fc[gy * Wc + gx];
            sf[buf][idx] = v;
        }
        __syncthreads();
        if (valid) {
            float a = 0.f;
#pragma unroll
            for (int i = 0; i < 7; i++)
#pragma unroll
                for (int j = 0; j < 7; j++)
                    a += kv[i * 7 + j] * sf[buf][(tyi + i) * FT + txi + j];
            ob[cl * HWc + y * Wc + x] = a;
        }
    }
}

// ---------------------------------------------------------------------------
extern "C" void kernel_launch(void* const* d_in, const int* in_sizes, int n_in,
                              void* d_out, int out_size)
{
    const float* cur_low  = (const float*)d_in[0];
    const float* key_low  = (const float*)d_in[1];
    const float* key_high = (const float*)d_in[2];
    const float* w_reduce = (const float*)d_in[3];
    const float* b_reduce = (const float*)d_in[4];
    const float* w_conv2  = (const float*)d_in[5];
    const float* b_conv2  = (const float*)d_in[6];
    const float* w_conv3  = (const float*)d_in[7];
    const float* b_conv3  = (const float*)d_in[8];
    float* out = (float*)d_out;

    float *cur_up, *key_up, *concat, *x2, *kern, *wrT, *w2T;
    cudaGetSymbolAddress((void**)&cur_up, g_cur_up);
    cudaGetSymbolAddress((void**)&key_up, g_key_up);
    cudaGetSymbolAddress((void**)&concat, g_concat);
    cudaGetSymbolAddress((void**)&x2, g_x2);
    cudaGetSymbolAddress((void**)&kern, g_kern);
    cudaGetSymbolAddress((void**)&wrT, g_wrT);
    cudaGetSymbolAddress((void**)&w2T, g_w2T);

    // weight pre-transpose (tiled)
    {
        dim3 blk(32, 8);
        dim3 g1((128 * 9 + 31) / 32, (256 + 31) / 32);
        transpose_w_kernel<<<g1, blk>>>(w_reduce, wrT, 256, 128 * 9);
        dim3 g2((512 * 9 + 31) / 32, (256 + 31) / 32);
        transpose_w_kernel<<<g2, blk>>>(w_conv2, w2T, 256, 512 * 9);
    }
    // upsample both low-feature tensors
    {
        int total = 2 * 128 * HWc;
        upsample_kernel<<<(total + 255) / 256, 256>>>(cur_low, cur_up, total);
        upsample_kernel<<<(total + 255) / 256, 256>>>(key_low, key_up, total);
    }
    // conv_reduce (shared weights), writing directly into concat layout
    {
        dim3 grid(9, 17, 8);
        conv3x3_relu_kernel<128><<<grid, 256>>>(
            cur_up, wrT, b_reduce, concat, 128 * HWc, 512 * HWc);
        conv3x3_relu_kernel<128><<<grid, 256>>>(
            key_up, wrT, b_reduce, concat + 256 * HWc, 128 * HWc, 512 * HWc);
    }
    // conv2: 512 -> 256
    {
        dim3 grid(9, 17, 8);
        conv3x3_relu_kernel<512><<<grid, 256>>>(
            concat, w2T, b_conv2, x2, 512 * HWc, 256 * HWc);
    }
    // conv3 (1x1, 256->49) + relu + softmax
    {
        int smem = 256 * 50 * sizeof(float);
        cudaFuncSetAttribute(conv3_softmax_kernel,
                             cudaFuncAttributeMaxDynamicSharedMemorySize, smem);
        int total = 2 * HWc;
        conv3_softmax_kernel<<<(total + 255) / 256, 256, smem>>>(
            x2, w_conv3, b_conv3, kern);
    }
    // spatially-variant 7x7 conv
    {
        dim3 grid(9, 9, 8);
        svconv_kernel<<<grid, 256>>>(key_high, kern, out);
    }
}